// round 2
// baseline (speedup 1.0000x reference)
#include <cuda_runtime.h>
#include <math.h>

#define NBODY 512
#define NVERT 6890
#define NJ 24
#define NCOL (NVERT*3)       /* 20670 rows of Pext: row = v*3+c */
#define KP 224               /* 207 pose + 10 beta + 1 template + 6 zero pad */
#define NCOLPAD 20736        /* 216 v-tiles * 96 cols */

#define BN 64                /* bodies per block tile */
#define BV 32                /* vertices per block tile */

// Scratch (device globals — no allocation in kernel_launch)
__device__ float d_Pext[NCOLPAD * KP];      // ~18.6 MB, padded rows stay 0 (bss)
__device__ float d_Lext[NBODY * KP];
__device__ float d_Gm[NBODY * NJ * 12];     // rows 0..2 of each 4x4, translation adjusted
__device__ float d_JS[NJ * 3 * 10];
__device__ float d_Jt[NJ * 3];

__constant__ int c_par[NJ] = {0,0,0,0,1,2,3,4,5,6,7,8,9,9,9,12,13,14,16,17,18,19,20,21};

// ---------------------------------------------------------------------------
// Pack posedirs/shapedirs/v_template into one K=224 "B" matrix (row = v*3+c)
// ---------------------------------------------------------------------------
__global__ void build_pext_kernel(const float* __restrict__ posedirs,
                                  const float* __restrict__ shapedirs,
                                  const float* __restrict__ v_template)
{
    int idx = blockIdx.x * blockDim.x + threadIdx.x;
    if (idx >= NCOLPAD * KP) return;
    int row = idx / KP;
    int k   = idx - row * KP;
    float val = 0.f;
    if (row < NCOL) {
        if (k < 207)       val = posedirs[row * 207 + k];
        else if (k < 217)  val = shapedirs[row * 10 + (k - 207)];
        else if (k == 217) val = v_template[row];
    }
    d_Pext[idx] = val;
}

// ---------------------------------------------------------------------------
// Fold J_regressor into shape space once:  J[n,j,c] = Jt[j,c] + JS[j,c,:]·beta[n]
// ---------------------------------------------------------------------------
__global__ void calc_js_kernel(const float* __restrict__ Jreg,
                               const float* __restrict__ shapedirs,
                               const float* __restrict__ v_template)
{
    int j = blockIdx.x;
    float acc[33];
#pragma unroll
    for (int q = 0; q < 33; q++) acc[q] = 0.f;
    for (int v = threadIdx.x; v < NVERT; v += 256) {
        float jr = Jreg[j * NVERT + v];
#pragma unroll
        for (int c = 0; c < 3; c++) {
            acc[c * 11] += jr * v_template[v * 3 + c];
#pragma unroll
            for (int b = 0; b < 10; b++)
                acc[c * 11 + 1 + b] += jr * shapedirs[(v * 3 + c) * 10 + b];
        }
    }
    __shared__ float red[8][33];
    int lane = threadIdx.x & 31, wid = threadIdx.x >> 5;
#pragma unroll
    for (int q = 0; q < 33; q++) {
        float s = acc[q];
        for (int o = 16; o; o >>= 1) s += __shfl_down_sync(0xffffffffu, s, o);
        if (lane == 0) red[wid][q] = s;
    }
    __syncthreads();
    if (threadIdx.x < 33) {
        int q = threadIdx.x;
        float s = 0.f;
        for (int w = 0; w < 8; w++) s += red[w][q];
        int c = q / 11, r = q - c * 11;
        if (r == 0) d_Jt[j * 3 + c] = s;
        else        d_JS[(j * 3 + c) * 10 + (r - 1)] = s;
    }
}

// ---------------------------------------------------------------------------
// Per-body: Rodrigues, lrotmin->Lext, joint locations, kinematic chain, G'
// One warp per body.
// ---------------------------------------------------------------------------
__global__ void body_kernel(const float* __restrict__ beta,
                            const float* __restrict__ pose)
{
    int n = blockIdx.x;
    int lane = threadIdx.x;
    __shared__ float sR[NJ][9];
    __shared__ float sJ[NJ][3];
    __shared__ float sG[NJ][12];
    __shared__ float sBeta[10];

    if (lane < 10) sBeta[lane] = beta[n * 10 + lane];
    if (lane < NJ) {
        float x = pose[n * 72 + lane * 3 + 0];
        float y = pose[n * 72 + lane * 3 + 1];
        float z = pose[n * 72 + lane * 3 + 2];
        float th = sqrtf(x * x + y * y + z * z) + 1e-8f;
        float inv = 1.0f / th;
        x *= inv; y *= inv; z *= inv;
        float s, c;
        sincosf(th, &s, &c);
        float C = 1.0f - c;
        sR[lane][0] = c + C * x * x;     sR[lane][1] = C * x * y - s * z; sR[lane][2] = C * x * z + s * y;
        sR[lane][3] = C * x * y + s * z; sR[lane][4] = c + C * y * y;     sR[lane][5] = C * y * z - s * x;
        sR[lane][6] = C * x * z - s * y; sR[lane][7] = C * y * z + s * x; sR[lane][8] = c + C * z * z;
    }
    __syncwarp();

    // Lext row: [0..206] lrotmin, [207..216] beta, [217]=1, [218..223]=0
    for (int t = lane; t < 207; t += 32) {
        int jj = 1 + t / 9, e = t - (t / 9) * 9;
        d_Lext[n * KP + t] = sR[jj][e] - ((e == 0 || e == 4 || e == 8) ? 1.0f : 0.0f);
    }
    for (int t = lane; t < 17; t += 32) {
        int k = 207 + t;
        d_Lext[n * KP + k] = (t < 10) ? sBeta[t] : ((k == 217) ? 1.0f : 0.0f);
    }

    // joint locations
    for (int t = lane; t < 72; t += 32) {
        int jj = t / 3, c = t - jj * 3;
        float s = d_Jt[jj * 3 + c];
#pragma unroll
        for (int b = 0; b < 10; b++) s += d_JS[(jj * 3 + c) * 10 + b] * sBeta[b];
        sJ[jj][c] = s;
    }
    __syncwarp();

    // kinematic chain (rows 0..2 of 4x4; bottom row implicit 0001)
    if (lane < 12) {
        int r = lane >> 2, cc = lane & 3;
        sG[0][lane] = (cc < 3) ? sR[0][r * 3 + cc] : sJ[0][r];
    }
    __syncwarp();
    for (int i = 1; i < NJ; i++) {
        int p = c_par[i];
        float val = 0.f;
        if (lane < 12) {
            int r = lane >> 2, cc = lane & 3;
            float t0, t1, t2;
            if (cc < 3) { t0 = sR[i][cc]; t1 = sR[i][3 + cc]; t2 = sR[i][6 + cc]; }
            else { t0 = sJ[i][0] - sJ[p][0]; t1 = sJ[i][1] - sJ[p][1]; t2 = sJ[i][2] - sJ[p][2]; }
            val = sG[p][r * 4 + 0] * t0 + sG[p][r * 4 + 1] * t1 + sG[p][r * 4 + 2] * t2;
            if (cc == 3) val += sG[p][r * 4 + 3];
        }
        __syncwarp();
        if (lane < 12) sG[i][lane] = val;
        __syncwarp();
    }

    // remove rest-pose joint translation: t -= R_g * J
    for (int t = lane; t < 72; t += 32) {
        int jj = t / 3, r = t - jj * 3;
        float rj = sG[jj][r * 4 + 0] * sJ[jj][0] + sG[jj][r * 4 + 1] * sJ[jj][1]
                 + sG[jj][r * 4 + 2] * sJ[jj][2];
        sG[jj][r * 4 + 3] -= rj;
    }
    __syncwarp();
    for (int t = lane; t < NJ * 12; t += 32)
        d_Gm[n * NJ * 12 + t] = sG[t / 12][t - (t / 12) * 12];
}

// ---------------------------------------------------------------------------
// Main fused kernel: v_posed GEMM (K=224) + LBS, all in registers/smem.
// Block tile: 64 bodies x 32 vertices (96 GEMM cols). Thread: 4 bodies x 2 verts.
// ---------------------------------------------------------------------------
__global__ void __launch_bounds__(256)
smpl_main_kernel(const float* __restrict__ weights, float* __restrict__ out)
{
    __shared__ float As[32][65];   // [k][body]
    __shared__ float Bs[32][97];   // [k][col]
    __shared__ float Ws[32][25];   // [vert][joint]
    __shared__ float Gs[64][76];   // [body][6 joints * 12]

    int tid = threadIdx.x;
    int tx = tid & 15, ty = tid >> 4;
    int nBase = blockIdx.y * BN;
    int vBase = blockIdx.x * BV;
    int colBase = vBase * 3;

    float vp[4][6];
#pragma unroll
    for (int i = 0; i < 4; i++)
#pragma unroll
        for (int j = 0; j < 6; j++) vp[i][j] = 0.f;

    // ---- Phase 1: v_posed = Lext @ Pext^T (template/shape folded into K) ----
    for (int k0 = 0; k0 < KP; k0 += 32) {
#pragma unroll
        for (int t = 0; t < 8; t++) {
            int idx = tid + t * 256;
            int nl = idx >> 5, kk = idx & 31;
            As[kk][nl] = d_Lext[(nBase + nl) * KP + k0 + kk];
        }
#pragma unroll
        for (int t = 0; t < 12; t++) {
            int idx = tid + t * 256;
            int cl = idx >> 5, kk = idx & 31;
            Bs[kk][cl] = d_Pext[(size_t)(colBase + cl) * KP + k0 + kk];
        }
        __syncthreads();
#pragma unroll
        for (int kk = 0; kk < 32; kk++) {
            float a0 = As[kk][ty * 4 + 0];
            float a1 = As[kk][ty * 4 + 1];
            float a2 = As[kk][ty * 4 + 2];
            float a3 = As[kk][ty * 4 + 3];
            float b[6];
#pragma unroll
            for (int j = 0; j < 6; j++) b[j] = Bs[kk][tx * 6 + j];
#pragma unroll
            for (int j = 0; j < 6; j++) {
                vp[0][j] += a0 * b[j];
                vp[1][j] += a1 * b[j];
                vp[2][j] += a2 * b[j];
                vp[3][j] += a3 * b[j];
            }
        }
        __syncthreads();
    }

    // ---- Phase 2: linear blend skinning ----
    for (int t = tid; t < BV * 24; t += 256) {
        int vl = t / 24, j2 = t - vl * 24;
        int v = vBase + vl;
        Ws[vl][j2] = (v < NVERT) ? weights[v * 24 + j2] : 0.f;
    }

    float o[4][6];
#pragma unroll
    for (int i = 0; i < 4; i++)
#pragma unroll
        for (int j = 0; j < 6; j++) o[i][j] = 0.f;

    for (int jc = 0; jc < 4; jc++) {
        __syncthreads();
        for (int t = tid; t < 64 * 72; t += 256) {
            int nl = t / 72, e = t - nl * 72;
            Gs[nl][e] = d_Gm[(nBase + nl) * 288 + jc * 72 + e];
        }
        __syncthreads();
#pragma unroll
        for (int jj = 0; jj < 6; jj++) {
#pragma unroll
            for (int i = 0; i < 4; i++) {
                const float* g = &Gs[ty * 4 + i][jj * 12];
                float g0 = g[0], g1 = g[1], g2 = g[2], g3 = g[3];
                float g4 = g[4], g5 = g[5], g6 = g[6], g7 = g[7];
                float g8 = g[8], g9 = g[9], g10 = g[10], g11 = g[11];
#pragma unroll
                for (int vv = 0; vv < 2; vv++) {
                    float w = Ws[tx * 2 + vv][jc * 6 + jj];
                    float x = vp[i][vv * 3 + 0], y = vp[i][vv * 3 + 1], z = vp[i][vv * 3 + 2];
                    o[i][vv * 3 + 0] += w * (g0 * x + g1 * y + g2 * z + g3);
                    o[i][vv * 3 + 1] += w * (g4 * x + g5 * y + g6 * z + g7);
                    o[i][vv * 3 + 2] += w * (g8 * x + g9 * y + g10 * z + g11);
                }
            }
        }
    }

    // ---- Store ----
#pragma unroll
    for (int i = 0; i < 4; i++) {
        int n = nBase + ty * 4 + i;
#pragma unroll
        for (int vv = 0; vv < 2; vv++) {
            int v = vBase + tx * 2 + vv;
            if (v < NVERT) {
                size_t b = ((size_t)n * NVERT + v) * 3;
                out[b + 0] = o[i][vv * 3 + 0];
                out[b + 1] = o[i][vv * 3 + 1];
                out[b + 2] = o[i][vv * 3 + 2];
            }
        }
    }
}

// ---------------------------------------------------------------------------
extern "C" void kernel_launch(void* const* d_in, const int* in_sizes, int n_in,
                              void* d_out, int out_size)
{
    const float* beta        = (const float*)d_in[0];
    const float* pose        = (const float*)d_in[1];
    const float* v_template  = (const float*)d_in[2];
    const float* shapedirs   = (const float*)d_in[3];
    const float* posedirs    = (const float*)d_in[4];
    const float* J_regressor = (const float*)d_in[5];
    const float* weights     = (const float*)d_in[6];
    float* out = (float*)d_out;

    build_pext_kernel<<<(NCOLPAD * KP + 255) / 256, 256>>>(posedirs, shapedirs, v_template);
    calc_js_kernel<<<NJ, 256>>>(J_regressor, shapedirs, v_template);
    body_kernel<<<NBODY, 32>>>(beta, pose);
    smpl_main_kernel<<<dim3((NVERT + BV - 1) / BV, NBODY / BN), 256>>>(weights, out);
}

// round 3
// speedup vs baseline: 1.8560x; 1.8560x over previous
#include <cuda_runtime.h>
#include <math.h>

#define NBODY 512
#define NVERT 6890
#define NJ 24
#define NCOL (NVERT*3)       /* 20670 cols of PextT */
#define KP 224               /* 207 pose + 10 beta + 1 template + 6 zero pad */
#define NCOLPAD 20736        /* 216 v-tiles * 96 cols */
#define BN 64                /* bodies per block tile */
#define BV 32                /* vertices per block tile */

typedef unsigned long long ull;

// Scratch (device globals — no allocation in kernel_launch)
__device__ float d_PextT[(size_t)KP * NCOLPAD]; // [k][col]  ~18.6 MB
__device__ float d_LextT[KP * NBODY];           // [k][body]
__device__ float d_Gm[NBODY * NJ * 12];
__device__ float d_JS[NJ * 3 * 10];
__device__ float d_Jt[NJ * 3];

__constant__ int c_par[NJ] = {0,0,0,0,1,2,3,4,5,6,7,8,9,9,9,12,13,14,16,17,18,19,20,21};

// ---- packed f32x2 helpers -------------------------------------------------
__device__ __forceinline__ ull ffma2(ull a, ull b, ull c) {
    ull d;
    asm("fma.rn.f32x2 %0, %1, %2, %3;" : "=l"(d) : "l"(a), "l"(b), "l"(c));
    return d;
}
__device__ __forceinline__ ull dup2(float x) {
    ull d; unsigned u = __float_as_uint(x);
    asm("mov.b64 %0, {%1, %1};" : "=l"(d) : "r"(u));
    return d;
}
__device__ __forceinline__ float2 unpack2(ull p) {
    float2 r;
    asm("mov.b64 {%0, %1}, %2;" : "=f"(r.x), "=f"(r.y) : "l"(p));
    return r;
}

// ---------------------------------------------------------------------------
// Tiled transpose-pack: PextT[k][col] from posedirs/shapedirs/v_template.
// Reads coalesced along k, writes coalesced along col.
// ---------------------------------------------------------------------------
__global__ void build_pextT_kernel(const float* __restrict__ posedirs,
                                   const float* __restrict__ shapedirs,
                                   const float* __restrict__ v_template)
{
    __shared__ float tile[32][33];
    int rbase = blockIdx.x * 32;   // col base
    int kbase = blockIdx.y * 32;   // k base
    int tx = threadIdx.x, ty = threadIdx.y;   // 32 x 8
#pragma unroll
    for (int i = 0; i < 4; i++) {
        int row = rbase + ty * 4 + i;
        int k = kbase + tx;
        float v = 0.f;
        if (row < NCOL) {
            if (k < 207)       v = posedirs[row * 207 + k];
            else if (k < 217)  v = shapedirs[row * 10 + (k - 207)];
            else if (k == 217) v = v_template[row];
        }
        tile[ty * 4 + i][tx] = v;
    }
    __syncthreads();
#pragma unroll
    for (int i = 0; i < 4; i++) {
        int k = kbase + ty * 4 + i;
        int row = rbase + tx;
        d_PextT[(size_t)k * NCOLPAD + row] = tile[tx][ty * 4 + i];
    }
}

// ---------------------------------------------------------------------------
// Fold J_regressor into shape space once
// ---------------------------------------------------------------------------
__global__ void calc_js_kernel(const float* __restrict__ Jreg,
                               const float* __restrict__ shapedirs,
                               const float* __restrict__ v_template)
{
    int j = blockIdx.x;
    float acc[33];
#pragma unroll
    for (int q = 0; q < 33; q++) acc[q] = 0.f;
    for (int v = threadIdx.x; v < NVERT; v += 512) {
        float jr = Jreg[j * NVERT + v];
#pragma unroll
        for (int c = 0; c < 3; c++) {
            acc[c * 11] += jr * v_template[v * 3 + c];
#pragma unroll
            for (int b = 0; b < 10; b++)
                acc[c * 11 + 1 + b] += jr * shapedirs[(v * 3 + c) * 10 + b];
        }
    }
    __shared__ float red[16][33];
    int lane = threadIdx.x & 31, wid = threadIdx.x >> 5;
#pragma unroll
    for (int q = 0; q < 33; q++) {
        float s = acc[q];
        for (int o = 16; o; o >>= 1) s += __shfl_down_sync(0xffffffffu, s, o);
        if (lane == 0) red[wid][q] = s;
    }
    __syncthreads();
    if (threadIdx.x < 33) {
        int q = threadIdx.x;
        float s = 0.f;
        for (int w = 0; w < 16; w++) s += red[w][q];
        int c = q / 11, r = q - c * 11;
        if (r == 0) d_Jt[j * 3 + c] = s;
        else        d_JS[(j * 3 + c) * 10 + (r - 1)] = s;
    }
}

// ---------------------------------------------------------------------------
// Per-body: Rodrigues, LextT, joints, kinematic chain, G'. One warp per body.
// ---------------------------------------------------------------------------
__global__ void body_kernel(const float* __restrict__ beta,
                            const float* __restrict__ pose)
{
    int n = blockIdx.x;
    int lane = threadIdx.x;
    __shared__ float sR[NJ][9];
    __shared__ float sJ[NJ][3];
    __shared__ float sG[NJ][12];
    __shared__ float sBeta[10];

    if (lane < 10) sBeta[lane] = beta[n * 10 + lane];
    if (lane < NJ) {
        float x = pose[n * 72 + lane * 3 + 0];
        float y = pose[n * 72 + lane * 3 + 1];
        float z = pose[n * 72 + lane * 3 + 2];
        float th = sqrtf(x * x + y * y + z * z) + 1e-8f;
        float inv = 1.0f / th;
        x *= inv; y *= inv; z *= inv;
        float s, c;
        sincosf(th, &s, &c);
        float C = 1.0f - c;
        sR[lane][0] = c + C * x * x;     sR[lane][1] = C * x * y - s * z; sR[lane][2] = C * x * z + s * y;
        sR[lane][3] = C * x * y + s * z; sR[lane][4] = c + C * y * y;     sR[lane][5] = C * y * z - s * x;
        sR[lane][6] = C * x * z - s * y; sR[lane][7] = C * y * z + s * x; sR[lane][8] = c + C * z * z;
    }
    __syncwarp();

    // LextT column n: [0..206] lrotmin, [207..216] beta, [217]=1, [218..223]=0
    for (int t = lane; t < 207; t += 32) {
        int jj = 1 + t / 9, e = t - (t / 9) * 9;
        d_LextT[t * NBODY + n] = sR[jj][e] - ((e == 0 || e == 4 || e == 8) ? 1.0f : 0.0f);
    }
    for (int t = lane; t < 17; t += 32) {
        int k = 207 + t;
        d_LextT[k * NBODY + n] = (t < 10) ? sBeta[t] : ((k == 217) ? 1.0f : 0.0f);
    }

    for (int t = lane; t < 72; t += 32) {
        int jj = t / 3, c = t - jj * 3;
        float s = d_Jt[jj * 3 + c];
#pragma unroll
        for (int b = 0; b < 10; b++) s += d_JS[(jj * 3 + c) * 10 + b] * sBeta[b];
        sJ[jj][c] = s;
    }
    __syncwarp();

    if (lane < 12) {
        int r = lane >> 2, cc = lane & 3;
        sG[0][lane] = (cc < 3) ? sR[0][r * 3 + cc] : sJ[0][r];
    }
    __syncwarp();
    for (int i = 1; i < NJ; i++) {
        int p = c_par[i];
        float val = 0.f;
        if (lane < 12) {
            int r = lane >> 2, cc = lane & 3;
            float t0, t1, t2;
            if (cc < 3) { t0 = sR[i][cc]; t1 = sR[i][3 + cc]; t2 = sR[i][6 + cc]; }
            else { t0 = sJ[i][0] - sJ[p][0]; t1 = sJ[i][1] - sJ[p][1]; t2 = sJ[i][2] - sJ[p][2]; }
            val = sG[p][r * 4 + 0] * t0 + sG[p][r * 4 + 1] * t1 + sG[p][r * 4 + 2] * t2;
            if (cc == 3) val += sG[p][r * 4 + 3];
        }
        __syncwarp();
        if (lane < 12) sG[i][lane] = val;
        __syncwarp();
    }

    for (int t = lane; t < 72; t += 32) {
        int jj = t / 3, r = t - jj * 3;
        float rj = sG[jj][r * 4 + 0] * sJ[jj][0] + sG[jj][r * 4 + 1] * sJ[jj][1]
                 + sG[jj][r * 4 + 2] * sJ[jj][2];
        sG[jj][r * 4 + 3] -= rj;
    }
    __syncwarp();
    for (int t = lane; t < NJ * 12; t += 32)
        d_Gm[n * NJ * 12 + t] = sG[t / 12][t - (t / 12) * 12];
}

// ---------------------------------------------------------------------------
// Main fused kernel, f32x2-packed over body pairs.
// Block: 128 threads = 16 tx (col) x 8 ty (body). Thread: 8 bodies x 6 cols.
// Block tile: 64 bodies x 96 cols (32 verts).
// ---------------------------------------------------------------------------
__global__ void __launch_bounds__(128)
smpl_main_kernel(const float* __restrict__ weights, float* __restrict__ out)
{
    __shared__ __align__(16) float As[32][72];    // [k][body], pairs pre-adjacent
    __shared__ __align__(16) float Bs[32][100];   // [k][col]
    __shared__ float Ws[32][28];                  // [vert][joint]
    __shared__ float2 Gs2[32 * 72];               // [body-pair][6 joints * 12] interleaved

    int tid = threadIdx.x;
    int tx = tid & 15, ty = tid >> 4;
    int nBase = blockIdx.y * BN;
    int vBase = blockIdx.x * BV;
    int colBase = vBase * 3;

    ull vp2[4][6];   // 4 body-pairs x 6 cols
#pragma unroll
    for (int p = 0; p < 4; p++)
#pragma unroll
        for (int j = 0; j < 6; j++) vp2[p][j] = 0ull;

    // ---- Phase 1: v_posed = Lext @ Pext^T, packed over body pairs ----
    for (int k0 = 0; k0 < KP; k0 += 32) {
#pragma unroll
        for (int t = 0; t < 4; t++) {
            int idx = tid + t * 128;
            int kk = idx >> 4, c4 = idx & 15;
            *(float4*)&As[kk][c4 * 4] =
                *(const float4*)&d_LextT[(k0 + kk) * NBODY + nBase + c4 * 4];
        }
#pragma unroll
        for (int t = 0; t < 6; t++) {
            int idx = tid + t * 128;
            int kk = idx / 24, c4 = idx - kk * 24;
            *(float4*)&Bs[kk][c4 * 4] =
                *(const float4*)&d_PextT[(size_t)(k0 + kk) * NCOLPAD + colBase + c4 * 4];
        }
        __syncthreads();
#pragma unroll
        for (int kk = 0; kk < 32; kk++) {
            ulonglong2 A0 = *(const ulonglong2*)&As[kk][ty * 8];
            ulonglong2 A1 = *(const ulonglong2*)&As[kk][ty * 8 + 4];
            ull pa0 = A0.x, pa1 = A0.y, pa2 = A1.x, pa3 = A1.y;
            float2 b01 = *(const float2*)&Bs[kk][tx * 6];
            float2 b23 = *(const float2*)&Bs[kk][tx * 6 + 2];
            float2 b45 = *(const float2*)&Bs[kk][tx * 6 + 4];
            ull bd[6];
            bd[0] = dup2(b01.x); bd[1] = dup2(b01.y);
            bd[2] = dup2(b23.x); bd[3] = dup2(b23.y);
            bd[4] = dup2(b45.x); bd[5] = dup2(b45.y);
#pragma unroll
            for (int j = 0; j < 6; j++) {
                vp2[0][j] = ffma2(pa0, bd[j], vp2[0][j]);
                vp2[1][j] = ffma2(pa1, bd[j], vp2[1][j]);
                vp2[2][j] = ffma2(pa2, bd[j], vp2[2][j]);
                vp2[3][j] = ffma2(pa3, bd[j], vp2[3][j]);
            }
        }
        __syncthreads();
    }

    // ---- Phase 2: LBS, packed over body pairs ----
    for (int t = tid; t < BV * 24; t += 128) {
        int vl = t / 24, j2 = t - vl * 24;
        int v = vBase + vl;
        Ws[vl][j2] = (v < NVERT) ? weights[v * 24 + j2] : 0.f;
    }

    ull o2[4][6];
#pragma unroll
    for (int p = 0; p < 4; p++)
#pragma unroll
        for (int j = 0; j < 6; j++) o2[p][j] = 0ull;

    for (int jc = 0; jc < 4; jc++) {
        __syncthreads();
        for (int t = tid; t < 64 * 72; t += 128) {
            int nl = t / 72, e = t - nl * 72;
            float g = d_Gm[(nBase + nl) * 288 + jc * 72 + e];
            if (nl & 1) Gs2[(nl >> 1) * 72 + e].y = g;
            else        Gs2[(nl >> 1) * 72 + e].x = g;
        }
        __syncthreads();
#pragma unroll
        for (int jj = 0; jj < 6; jj++) {
#pragma unroll
            for (int q = 0; q < 4; q++) {
                const ull* g = (const ull*)&Gs2[(ty * 4 + q) * 72 + jj * 12];
                ull g0 = g[0], g1 = g[1], g2 = g[2],  g3 = g[3];
                ull g4 = g[4], g5 = g[5], g6 = g[6],  g7 = g[7];
                ull g8 = g[8], g9 = g[9], g10 = g[10], g11 = g[11];
#pragma unroll
                for (int vv = 0; vv < 2; vv++) {
                    ull wd = dup2(Ws[tx * 2 + vv][jc * 6 + jj]);
                    ull x = vp2[q][vv * 3 + 0];
                    ull y = vp2[q][vv * 3 + 1];
                    ull z = vp2[q][vv * 3 + 2];
                    ull t0 = ffma2(g0, x, ffma2(g1, y, ffma2(g2,  z, g3)));
                    ull t1 = ffma2(g4, x, ffma2(g5, y, ffma2(g6,  z, g7)));
                    ull t2 = ffma2(g8, x, ffma2(g9, y, ffma2(g10, z, g11)));
                    o2[q][vv * 3 + 0] = ffma2(wd, t0, o2[q][vv * 3 + 0]);
                    o2[q][vv * 3 + 1] = ffma2(wd, t1, o2[q][vv * 3 + 1]);
                    o2[q][vv * 3 + 2] = ffma2(wd, t2, o2[q][vv * 3 + 2]);
                }
            }
        }
    }

    // ---- Store (unpack body pairs) ----
#pragma unroll
    for (int q = 0; q < 4; q++) {
        int n0 = nBase + ty * 8 + 2 * q;
#pragma unroll
        for (int vv = 0; vv < 2; vv++) {
            int v = vBase + tx * 2 + vv;
            if (v < NVERT) {
                size_t b0 = ((size_t)n0 * NVERT + v) * 3;
                size_t b1 = ((size_t)(n0 + 1) * NVERT + v) * 3;
#pragma unroll
                for (int c = 0; c < 3; c++) {
                    float2 pr = unpack2(o2[q][vv * 3 + c]);
                    out[b0 + c] = pr.x;
                    out[b1 + c] = pr.y;
                }
            }
        }
    }
}

// ---------------------------------------------------------------------------
extern "C" void kernel_launch(void* const* d_in, const int* in_sizes, int n_in,
                              void* d_out, int out_size)
{
    const float* beta        = (const float*)d_in[0];
    const float* pose        = (const float*)d_in[1];
    const float* v_template  = (const float*)d_in[2];
    const float* shapedirs   = (const float*)d_in[3];
    const float* posedirs    = (const float*)d_in[4];
    const float* J_regressor = (const float*)d_in[5];
    const float* weights     = (const float*)d_in[6];
    float* out = (float*)d_out;

    build_pextT_kernel<<<dim3(NCOLPAD / 32, KP / 32), dim3(32, 8)>>>(posedirs, shapedirs, v_template);
    calc_js_kernel<<<NJ, 512>>>(J_regressor, shapedirs, v_template);
    body_kernel<<<NBODY, 32>>>(beta, pose);
    smpl_main_kernel<<<dim3((NVERT + BV - 1) / BV, NBODY / BN), 128>>>(weights, out);
}